// round 11
// baseline (speedup 1.0000x reference)
#include <cuda_runtime.h>
#include <cuda_fp16.h>

#define NN 100000
#define EE 1600000
#define HH 64

typedef unsigned long long ull;
typedef unsigned int uint;

// Scratch (device globals; no allocation allowed)
__device__ float g_h[NN * HH];
__device__ float g_agg[NN * HH];
__device__ uint  g_h16[(size_t)NN * 32];    // fp16 shadow of h (2 halves per uint)
__device__ uint  g_eah[(size_t)EE * 32];    // fp16 edge_attr, DST-SORTED order
__device__ int   g_deg[NN];
__device__ int   g_row[NN + 1];
__device__ int   g_cur[NN];
__device__ int   g_sidx[EE];                // src per sorted slot
__device__ int   g_eord[EE];                // original edge id per sorted slot

__device__ __forceinline__ float frelu(float x) { return x > 0.f ? x : 0.f; }

// ---- packed f32x2 helpers (FFMA2 — only reachable via PTX) -----------------
__device__ __forceinline__ ull pk2(float lo, float hi) {
    ull r;
    asm("mov.b64 %0, {%1,%2};" : "=l"(r) : "f"(lo), "f"(hi));
    return r;
}
__device__ __forceinline__ void upk2(ull v, float& lo, float& hi) {
    asm("mov.b64 {%0,%1}, %2;" : "=f"(lo), "=f"(hi) : "l"(v));
}
__device__ __forceinline__ ull ffma2(ull a, ull b, ull c) {
    ull d;
    asm("fma.rn.f32x2 %0, %1, %2, %3;" : "=l"(d) : "l"(a), "l"(b), "l"(c));
    return d;
}

__device__ __forceinline__ uint h2_bits(float a, float b) {
    __half2 h = __floats2half2_rn(a, b);
    return *reinterpret_cast<uint*>(&h);
}
__device__ __forceinline__ float2 bits_h2f(uint u) {
    __half2 h = *reinterpret_cast<__half2*>(&u);
    return __half22float2(h);
}

// ---------------------------------------------------------------------------
// CSR build: zero + histogram + single-block scan + scatter
// ---------------------------------------------------------------------------
__global__ void zero_deg_kernel(int* deg) {
    int i = blockIdx.x * 256 + threadIdx.x;
    if (i < NN) deg[i] = 0;
}

__global__ void hist_kernel(const int* __restrict__ dst, int* __restrict__ deg) {
    int e = blockIdx.x * 256 + threadIdx.x;
    if (e < EE) atomicAdd(&deg[dst[e]], 1);
}

// one block, 1024 threads; each thread scans a contiguous chunk
__global__ void scan_kernel(const int* __restrict__ deg,
                            int* __restrict__ row, int* __restrict__ cur) {
    __shared__ int ssum[1024];
    const int tid = threadIdx.x;
    const int CH = (NN + 1024) / 1024 + 1;   // chunk covers NN+1 indices
    int start = tid * CH;

    int s = 0;
    for (int i = 0; i < CH; i++) {
        int idx = start + i;
        if (idx < NN) s += deg[idx];
    }
    int val = s;
    ssum[tid] = s;
    __syncthreads();
    for (int off = 1; off < 1024; off <<= 1) {
        int t = (tid >= off) ? ssum[tid - off] : 0;
        __syncthreads();
        ssum[tid] += t;
        __syncthreads();
    }
    int run = ssum[tid] - val;   // exclusive prefix of this chunk
    for (int i = 0; i < CH; i++) {
        int idx = start + i;
        if (idx < NN) {
            row[idx] = run;
            cur[idx] = run;
            run += deg[idx];
        } else if (idx == NN) {
            row[NN] = run;
        }
    }
}

__global__ void scatter_kernel(const int* __restrict__ src, const int* __restrict__ dst,
                               int* __restrict__ cur,
                               int* __restrict__ sidx, int* __restrict__ eord) {
    int e = blockIdx.x * 256 + threadIdx.x;
    if (e >= EE) return;
    int d = dst[e];
    int p = atomicAdd(&cur[d], 1);
    sidx[p] = src[e];
    eord[p] = e;
}

// ---------------------------------------------------------------------------
// Edge pass 1 (warp per dst node, NO atomics): reads fp32 ea via eord (random),
// converts+stores eah in sorted order (sequential), accumulates msg in regs,
// writes agg = sum + h once, coalesced. Lane l owns dims (2l, 2l+1).
// ---------------------------------------------------------------------------
__global__ void __launch_bounds__(256) edge_agg_first(
    const uint* __restrict__ h16u,
    const float2* __restrict__ ea2,
    const int* __restrict__ eord,
    const int* __restrict__ sidx,
    const int* __restrict__ row,
    const float2* __restrict__ h2,
    float2* __restrict__ agg2,
    uint* __restrict__ eahu)
{
    int d = blockIdx.x * 8 + (threadIdx.x >> 5);
    if (d >= NN) return;
    int l = threadIdx.x & 31;

    int beg = __ldg(&row[d]);
    int end = __ldg(&row[d + 1]);

    float2 acc = make_float2(0.f, 0.f);
    for (int i = beg; i < end; i++) {
        int s = __ldg(&sidx[i]);
        int e = __ldg(&eord[i]);
        uint hu = __ldg(&h16u[(size_t)s * 32 + l]);
        float2 av = __ldcs(&ea2[(size_t)e * 32 + l]);
        __stcs(&eahu[(size_t)i * 32 + l], h2_bits(av.x, av.y));
        float2 hv = bits_h2f(hu);
        acc.x += frelu(av.x + hv.x);
        acc.y += frelu(av.y + hv.y);
    }
    float2 hr = h2[(size_t)d * 32 + l];
    agg2[(size_t)d * 32 + l] = make_float2(acc.x + hr.x, acc.y + hr.y);
}

// ---------------------------------------------------------------------------
// Edge passes 2-3: eah read sequentially (sorted), h16 gathers, no atomics.
// ---------------------------------------------------------------------------
__global__ void __launch_bounds__(256) edge_agg_half(
    const uint* __restrict__ h16u,
    const uint* __restrict__ eahu,
    const int* __restrict__ sidx,
    const int* __restrict__ row,
    const float2* __restrict__ h2,
    float2* __restrict__ agg2)
{
    int d = blockIdx.x * 8 + (threadIdx.x >> 5);
    if (d >= NN) return;
    int l = threadIdx.x & 31;

    int beg = __ldg(&row[d]);
    int end = __ldg(&row[d + 1]);

    float2 acc = make_float2(0.f, 0.f);
    for (int i = beg; i < end; i++) {
        int s = __ldg(&sidx[i]);
        uint au = __ldcs(&eahu[(size_t)i * 32 + l]);
        uint hu = __ldg(&h16u[(size_t)s * 32 + l]);
        float2 av = bits_h2f(au);
        float2 hv = bits_h2f(hu);
        acc.x += frelu(av.x + hv.x);
        acc.y += frelu(av.y + hv.y);
    }
    float2 hr = h2[(size_t)d * 32 + l];
    agg2[(size_t)d * 32 + l] = make_float2(acc.x + hr.x, acc.y + hr.y);
}

// ---------------------------------------------------------------------------
// Conv MLP kernel (R8 core, out2 removed): FFMA2, k-packed.
// out1 = relu_opt(relu(in@W1+b1)@W2+b2) + resid; optional fp16 shadow write.
// ---------------------------------------------------------------------------
#define MLP_SMEM_FLOATS (4096 + 4096 + 64 + 64 + 64 * 64)
__global__ void __launch_bounds__(256) mlp_kernel(
    const float* __restrict__ in,
    const float* __restrict__ resid,
    const float* __restrict__ W1, const float* __restrict__ b1,
    const float* __restrict__ W2, const float* __restrict__ b2,
    float* __restrict__ out1,
    __half* __restrict__ outh,
    int relu_out)
{
    extern __shared__ float sm[];
    float* sW1 = sm;              // 64*64
    float* sW2 = sm + 4096;       // 64*64
    float* sb1 = sm + 8192;       // 64
    float* sb2 = sm + 8256;       // 64
    float* sIn = sm + 8320;       // [node][64]

    const int tid = threadIdx.x;
    const int base = blockIdx.x * 64;

    for (int i = tid; i < 4096; i += 256) { sW1[i] = W1[i]; sW2[i] = W2[i]; }
    if (tid < 64) { sb1[tid] = b1[tid]; sb2[tid] = b2[tid]; }
    for (int i = tid; i < 64 * 16; i += 256) {
        int nd = i >> 4, c = i & 15;
        float4 v = make_float4(0.f, 0.f, 0.f, 0.f);
        if (base + nd < NN) v = ((const float4*)in)[(size_t)(base + nd) * 16 + c];
        ((float4*)(sIn + nd * 64))[c] = v;
    }
    __syncthreads();

    const int w = tid >> 5, l = tid & 31;
    const int ln0 = w * 8;

    ull acc0[8], acc1[8];
    {
        ull bb0 = pk2(sb1[l], 0.f);
        ull bb1 = pk2(sb1[l + 32], 0.f);
#pragma unroll
        for (int j = 0; j < 8; j++) { acc0[j] = bb0; acc1[j] = bb1; }
    }

#pragma unroll 8
    for (int k = 0; k < 64; k += 2) {
        ull w0p = pk2(sW1[k * 64 + l],      sW1[(k + 1) * 64 + l]);
        ull w1p = pk2(sW1[k * 64 + l + 32], sW1[(k + 1) * 64 + l + 32]);
#pragma unroll
        for (int j = 0; j < 8; j++) {
            ull vp = *(const ull*)&sIn[(ln0 + j) * 64 + k];
            acc0[j] = ffma2(vp, w0p, acc0[j]);
            acc1[j] = ffma2(vp, w1p, acc1[j]);
        }
    }

    __syncwarp();
#pragma unroll
    for (int j = 0; j < 8; j++) {
        float x0, x1, y0, y1;
        upk2(acc0[j], x0, x1);
        upk2(acc1[j], y0, y1);
        sIn[(ln0 + j) * 64 + l]      = frelu(x0 + x1);
        sIn[(ln0 + j) * 64 + l + 32] = frelu(y0 + y1);
    }
    __syncwarp();

    {
        ull bb0 = pk2(sb2[l], 0.f);
        ull bb1 = pk2(sb2[l + 32], 0.f);
#pragma unroll
        for (int j = 0; j < 8; j++) { acc0[j] = bb0; acc1[j] = bb1; }
    }

#pragma unroll 8
    for (int k = 0; k < 64; k += 2) {
        ull w0p = pk2(sW2[k * 64 + l],      sW2[(k + 1) * 64 + l]);
        ull w1p = pk2(sW2[k * 64 + l + 32], sW2[(k + 1) * 64 + l + 32]);
#pragma unroll
        for (int j = 0; j < 8; j++) {
            ull vp = *(const ull*)&sIn[(ln0 + j) * 64 + k];
            acc0[j] = ffma2(vp, w0p, acc0[j]);
            acc1[j] = ffma2(vp, w1p, acc1[j]);
        }
    }

#pragma unroll
    for (int j = 0; j < 8; j++) {
        int nd = base + ln0 + j;
        if (nd < NN) {
            float x0, x1, y0, y1;
            upk2(acc0[j], x0, x1);
            upk2(acc1[j], y0, y1);
            float v0 = x0 + x1, v1 = y0 + y1;
            if (relu_out) { v0 = frelu(v0); v1 = frelu(v1); }
            v0 += resid[(size_t)nd * 64 + l];
            v1 += resid[(size_t)nd * 64 + l + 32];
            out1[(size_t)nd * 64 + l] = v0;
            out1[(size_t)nd * 64 + l + 32] = v1;
            if (outh) {
                outh[(size_t)nd * 64 + l]      = __float2half_rn(v0);
                outh[(size_t)nd * 64 + l + 32] = __float2half_rn(v1);
            }
        }
    }
}

// ---------------------------------------------------------------------------
// Init kernel: h0 = relu(concat(emb[z],t)@rw1+rb1)@rw2+rb2 -> g_h + fp16 shadow
// ---------------------------------------------------------------------------
#define INIT_SMEM_FLOATS (65 * 64 + 4096 + 64 + 64 + 64 * 68)
__global__ void __launch_bounds__(256) init_kernel(
    const int* __restrict__ z,
    const float* __restrict__ t,
    const float* __restrict__ emb,
    const float* __restrict__ W1, const float* __restrict__ b1,
    const float* __restrict__ W2, const float* __restrict__ b2,
    float* __restrict__ out1,
    __half* __restrict__ outh)
{
    extern __shared__ float sm[];
    float* sW1 = sm;                    // 65*64 = 4160
    float* sW2 = sm + 4160;             // 64*64
    float* sb1 = sm + 8256;             // 64
    float* sb2 = sm + 8320;             // 64
    float* sIn = sm + 8384;             // [node][68] (65 used)
    __shared__ int sZ[64];

    const int tid = threadIdx.x;
    const int base = blockIdx.x * 64;

    for (int i = tid; i < 4160; i += 256) sW1[i] = W1[i];
    for (int i = tid; i < 4096; i += 256) sW2[i] = W2[i];
    if (tid < 64) {
        sb1[tid] = b1[tid]; sb2[tid] = b2[tid];
        int nd = base + tid;
        sZ[tid] = (nd < NN) ? z[nd] : 0;
        sIn[tid * 68 + 64] = (nd < NN) ? t[nd] : 0.f;
    }
    __syncthreads();

    for (int i = tid; i < 64 * 16; i += 256) {
        int nd = i >> 4, c = i & 15;
        float4 v = ((const float4*)emb)[(size_t)sZ[nd] * 16 + c];
        ((float4*)(sIn + nd * 68))[c] = v;
    }
    __syncthreads();

    const int w = tid >> 5, l = tid & 31;
    const int ln0 = w * 8;

    ull acc0[8], acc1[8];
    {
        ull bb0 = pk2(sb1[l], 0.f);
        ull bb1 = pk2(sb1[l + 32], 0.f);
#pragma unroll
        for (int j = 0; j < 8; j++) { acc0[j] = bb0; acc1[j] = bb1; }
    }

#pragma unroll 8
    for (int k = 0; k < 64; k += 2) {
        ull w0p = pk2(sW1[k * 64 + l],      sW1[(k + 1) * 64 + l]);
        ull w1p = pk2(sW1[k * 64 + l + 32], sW1[(k + 1) * 64 + l + 32]);
#pragma unroll
        for (int j = 0; j < 8; j++) {
            ull vp = *(const ull*)&sIn[(ln0 + j) * 68 + k];
            acc0[j] = ffma2(vp, w0p, acc0[j]);
            acc1[j] = ffma2(vp, w1p, acc1[j]);
        }
    }
    {   // k = 64 tail (the t column)
        ull w0p = pk2(sW1[64 * 64 + l],      sW1[64 * 64 + l]);
        ull w1p = pk2(sW1[64 * 64 + l + 32], sW1[64 * 64 + l + 32]);
#pragma unroll
        for (int j = 0; j < 8; j++) {
            ull vp = pk2(sIn[(ln0 + j) * 68 + 64], 0.f);
            acc0[j] = ffma2(vp, w0p, acc0[j]);
            acc1[j] = ffma2(vp, w1p, acc1[j]);
        }
    }

    __syncwarp();
#pragma unroll
    for (int j = 0; j < 8; j++) {
        float x0, x1, y0, y1;
        upk2(acc0[j], x0, x1);
        upk2(acc1[j], y0, y1);
        sIn[(ln0 + j) * 68 + l]      = frelu(x0 + x1);
        sIn[(ln0 + j) * 68 + l + 32] = frelu(y0 + y1);
    }
    __syncwarp();

    {
        ull bb0 = pk2(sb2[l], 0.f);
        ull bb1 = pk2(sb2[l + 32], 0.f);
#pragma unroll
        for (int j = 0; j < 8; j++) { acc0[j] = bb0; acc1[j] = bb1; }
    }

#pragma unroll 8
    for (int k = 0; k < 64; k += 2) {
        ull w0p = pk2(sW2[k * 64 + l],      sW2[(k + 1) * 64 + l]);
        ull w1p = pk2(sW2[k * 64 + l + 32], sW2[(k + 1) * 64 + l + 32]);
#pragma unroll
        for (int j = 0; j < 8; j++) {
            ull vp = *(const ull*)&sIn[(ln0 + j) * 68 + k];
            acc0[j] = ffma2(vp, w0p, acc0[j]);
            acc1[j] = ffma2(vp, w1p, acc1[j]);
        }
    }

#pragma unroll
    for (int j = 0; j < 8; j++) {
        int nd = base + ln0 + j;
        if (nd < NN) {
            float x0, x1, y0, y1;
            upk2(acc0[j], x0, x1);
            upk2(acc1[j], y0, y1);
            float v0 = x0 + x1, v1 = y0 + y1;
            out1[(size_t)nd * 64 + l] = v0;
            out1[(size_t)nd * 64 + l + 32] = v1;
            outh[(size_t)nd * 64 + l]      = __float2half_rn(v0);
            outh[(size_t)nd * 64 + l + 32] = __float2half_rn(v1);
        }
    }
}

// ---------------------------------------------------------------------------
// Launch
// ---------------------------------------------------------------------------
extern "C" void kernel_launch(void* const* d_in, const int* in_sizes, int n_in,
                              void* d_out, int out_size)
{
    const int*   z    = (const int*)  d_in[0];
    const int*   ei   = (const int*)  d_in[1];   // [2, E]: src = ei, dst = ei + EE
    const float* ea   = (const float*)d_in[2];
    const float* t    = (const float*)d_in[3];
    const float* emb  = (const float*)d_in[4];
    const float* rw1  = (const float*)d_in[5];
    const float* rb1  = (const float*)d_in[6];
    const float* rw2  = (const float*)d_in[7];
    const float* rb2  = (const float*)d_in[8];
    const float* cw1  = (const float*)d_in[9];
    const float* cb1  = (const float*)d_in[10];
    const float* cw2  = (const float*)d_in[11];
    const float* cb2  = (const float*)d_in[12];
    float* out = (float*)d_out;

    float *hp, *ap;  uint *h16, *ehp;
    int *deg, *rowp, *curp, *sidx, *eord;
    cudaGetSymbolAddress((void**)&hp,   g_h);
    cudaGetSymbolAddress((void**)&ap,   g_agg);
    cudaGetSymbolAddress((void**)&h16,  g_h16);
    cudaGetSymbolAddress((void**)&ehp,  g_eah);
    cudaGetSymbolAddress((void**)&deg,  g_deg);
    cudaGetSymbolAddress((void**)&rowp, g_row);
    cudaGetSymbolAddress((void**)&curp, g_cur);
    cudaGetSymbolAddress((void**)&sidx, g_sidx);
    cudaGetSymbolAddress((void**)&eord, g_eord);

    const int init_smem = INIT_SMEM_FLOATS * sizeof(float);
    const int mlp_smem  = MLP_SMEM_FLOATS * sizeof(float);
    cudaFuncSetAttribute(init_kernel, cudaFuncAttributeMaxDynamicSharedMemorySize, init_smem);
    cudaFuncSetAttribute(mlp_kernel,  cudaFuncAttributeMaxDynamicSharedMemorySize, mlp_smem);

    const int nblk_node  = (NN + 63) / 64;
    const int nblk_nodeZ = (NN + 255) / 256;
    const int nblk_edgeT = (EE + 255) / 256;
    const int nblk_agg   = (NN + 7) / 8;

    const int* srcp = ei;
    const int* dstp = ei + EE;

    // CSR build (deterministic work every call; values within tolerance)
    zero_deg_kernel<<<nblk_nodeZ, 256>>>(deg);
    hist_kernel<<<nblk_edgeT, 256>>>(dstp, deg);
    scan_kernel<<<1, 1024>>>(deg, rowp, curp);
    scatter_kernel<<<nblk_edgeT, 256>>>(srcp, dstp, curp, sidx, eord);

    // node init
    init_kernel<<<nblk_node, 256, init_smem>>>(z, t, emb, rw1, rb1, rw2, rb2,
                                               hp, (__half*)h16);

    for (int li = 0; li < 3; li++) {
        if (li == 0) {
            edge_agg_first<<<nblk_agg, 256>>>(h16, (const float2*)ea, eord, sidx,
                                              rowp, (const float2*)hp,
                                              (float2*)ap, ehp);
        } else {
            edge_agg_half<<<nblk_agg, 256>>>(h16, ehp, sidx, rowp,
                                             (const float2*)hp, (float2*)ap);
        }
        const float* W1 = cw1 + li * 4096;
        const float* b1 = cb1 + li * 64;
        const float* W2 = cw2 + li * 4096;
        const float* b2 = cb2 + li * 64;
        if (li < 2) {
            mlp_kernel<<<nblk_node, 256, mlp_smem>>>(ap, hp, W1, b1, W2, b2,
                                                     hp, (__half*)h16, 1);
        } else {
            mlp_kernel<<<nblk_node, 256, mlp_smem>>>(ap, hp, W1, b1, W2, b2,
                                                     out, nullptr, 0);
        }
    }
}

// round 12
// speedup vs baseline: 1.6191x; 1.6191x over previous
#include <cuda_runtime.h>

#define NN 100000
#define EE 1600000
#define HH 64

// Scratch (device globals; no allocation allowed)
__device__ float g_h[NN * HH];
__device__ float g_agg[NN * HH];

__device__ __forceinline__ float frelu(float x) { return x > 0.f ? x : 0.f; }

typedef unsigned long long ull;

// ---- packed f32x2 helpers (FFMA2 — only reachable via PTX) -----------------
__device__ __forceinline__ ull pk2(float lo, float hi) {
    ull r;
    asm("mov.b64 %0, {%1,%2};" : "=l"(r) : "f"(lo), "f"(hi));
    return r;
}
__device__ __forceinline__ void upk2(ull v, float& lo, float& hi) {
    asm("mov.b64 {%0,%1}, %2;" : "=f"(lo), "=f"(hi) : "l"(v));
}
__device__ __forceinline__ ull ffma2(ull a, ull b, ull c) {
    ull d;
    asm("fma.rn.f32x2 %0, %1, %2, %3;" : "=l"(d) : "l"(a), "l"(b), "l"(c));
    return d;
}

// ---------------------------------------------------------------------------
// Edge kernel (R8, measured best): msg = relu(h[src] + edge_attr);
// agg[dst] += msg. 8 threads/edge, 2 float4 chunks each. Exact grid (no
// bounds check). __ldcs on the 410MB edge_attr stream; __ldcg on h gathers.
// ---------------------------------------------------------------------------
__global__ void __launch_bounds__(256) edge_kernel(
    const float4* __restrict__ h,
    const float4* __restrict__ ea,
    const int* __restrict__ src,
    const int* __restrict__ dst,
    float4* __restrict__ agg)
{
    int t = blockIdx.x * 256 + threadIdx.x;
    int e = t >> 3;
    int c = t & 7;

    int s = __ldg(&src[e]);
    int d = __ldg(&dst[e]);

    float4 a0 = __ldcs(&ea[(size_t)e * 16 + c]);
    float4 a1 = __ldcs(&ea[(size_t)e * 16 + c + 8]);
    float4 h0 = __ldcg(&h[(size_t)s * 16 + c]);
    float4 h1 = __ldcg(&h[(size_t)s * 16 + c + 8]);

    float4 m0, m1;
    m0.x = frelu(a0.x + h0.x); m0.y = frelu(a0.y + h0.y);
    m0.z = frelu(a0.z + h0.z); m0.w = frelu(a0.w + h0.w);
    m1.x = frelu(a1.x + h1.x); m1.y = frelu(a1.y + h1.y);
    m1.z = frelu(a1.z + h1.z); m1.w = frelu(a1.w + h1.w);

    atomicAdd(&agg[(size_t)d * 16 + c], m0);
    atomicAdd(&agg[(size_t)d * 16 + c + 8], m1);
}

// ---------------------------------------------------------------------------
// Conv MLP kernel (R8 core + float4 weight staging): FFMA2, k-packed.
// out = relu_opt(relu(in@W1+b1)@W2+b2) + resid
// 256 threads = 8 warps, 64 nodes/block, 8 nodes/warp.
// ---------------------------------------------------------------------------
#define MLP_SMEM_FLOATS (4096 + 4096 + 64 + 64 + 64 * 64)
__global__ void __launch_bounds__(256) mlp_kernel(
    const float* __restrict__ in,
    const float* __restrict__ resid,
    const float* __restrict__ W1, const float* __restrict__ b1,
    const float* __restrict__ W2, const float* __restrict__ b2,
    float* __restrict__ out1, float* __restrict__ out2,
    int relu_out)
{
    extern __shared__ float sm[];
    float* sW1 = sm;              // 64*64
    float* sW2 = sm + 4096;       // 64*64
    float* sb1 = sm + 8192;       // 64
    float* sb2 = sm + 8256;       // 64
    float* sIn = sm + 8320;       // [node][64], natural layout

    const int tid = threadIdx.x;
    const int base = blockIdx.x * 64;

    // float4 staging: 8192 weight floats = 2048 float4 / 256 threads = 8 each
    {
        const float4* W1v = (const float4*)W1;
        const float4* W2v = (const float4*)W2;
        float4* sW1v = (float4*)sW1;
        float4* sW2v = (float4*)sW2;
#pragma unroll
        for (int i = 0; i < 4; i++) {
            sW1v[tid + 256 * i] = W1v[tid + 256 * i];
            sW2v[tid + 256 * i] = W2v[tid + 256 * i];
        }
    }
    if (tid < 64) { sb1[tid] = b1[tid]; sb2[tid] = b2[tid]; }
    for (int i = tid; i < 64 * 16; i += 256) {
        int nd = i >> 4, c = i & 15;
        float4 v = make_float4(0.f, 0.f, 0.f, 0.f);
        if (base + nd < NN) v = ((const float4*)in)[(size_t)(base + nd) * 16 + c];
        ((float4*)(sIn + nd * 64))[c] = v;
    }
    __syncthreads();

    const int w = tid >> 5, l = tid & 31;
    const int ln0 = w * 8;

    ull acc0[8], acc1[8];
    {
        ull bb0 = pk2(sb1[l], 0.f);
        ull bb1 = pk2(sb1[l + 32], 0.f);
#pragma unroll
        for (int j = 0; j < 8; j++) { acc0[j] = bb0; acc1[j] = bb1; }
    }

#pragma unroll 8
    for (int k = 0; k < 64; k += 2) {
        ull w0p = pk2(sW1[k * 64 + l],      sW1[(k + 1) * 64 + l]);
        ull w1p = pk2(sW1[k * 64 + l + 32], sW1[(k + 1) * 64 + l + 32]);
#pragma unroll
        for (int j = 0; j < 8; j++) {
            ull vp = *(const ull*)&sIn[(ln0 + j) * 64 + k];
            acc0[j] = ffma2(vp, w0p, acc0[j]);
            acc1[j] = ffma2(vp, w1p, acc1[j]);
        }
    }

    __syncwarp();
#pragma unroll
    for (int j = 0; j < 8; j++) {
        float x0, x1, y0, y1;
        upk2(acc0[j], x0, x1);
        upk2(acc1[j], y0, y1);
        sIn[(ln0 + j) * 64 + l]      = frelu(x0 + x1);
        sIn[(ln0 + j) * 64 + l + 32] = frelu(y0 + y1);
    }
    __syncwarp();

    {
        ull bb0 = pk2(sb2[l], 0.f);
        ull bb1 = pk2(sb2[l + 32], 0.f);
#pragma unroll
        for (int j = 0; j < 8; j++) { acc0[j] = bb0; acc1[j] = bb1; }
    }

#pragma unroll 8
    for (int k = 0; k < 64; k += 2) {
        ull w0p = pk2(sW2[k * 64 + l],      sW2[(k + 1) * 64 + l]);
        ull w1p = pk2(sW2[k * 64 + l + 32], sW2[(k + 1) * 64 + l + 32]);
#pragma unroll
        for (int j = 0; j < 8; j++) {
            ull vp = *(const ull*)&sIn[(ln0 + j) * 64 + k];
            acc0[j] = ffma2(vp, w0p, acc0[j]);
            acc1[j] = ffma2(vp, w1p, acc1[j]);
        }
    }

#pragma unroll
    for (int j = 0; j < 8; j++) {
        int nd = base + ln0 + j;
        if (nd < NN) {
            float x0, x1, y0, y1;
            upk2(acc0[j], x0, x1);
            upk2(acc1[j], y0, y1);
            float v0 = x0 + x1, v1 = y0 + y1;
            if (relu_out) { v0 = frelu(v0); v1 = frelu(v1); }
            v0 += resid[(size_t)nd * 64 + l];
            v1 += resid[(size_t)nd * 64 + l + 32];
            out1[(size_t)nd * 64 + l] = v0;
            out1[(size_t)nd * 64 + l + 32] = v1;
            if (out2) { out2[(size_t)nd * 64 + l] = v0; out2[(size_t)nd * 64 + l + 32] = v1; }
        }
    }
}

// ---------------------------------------------------------------------------
// Init kernel (R8 core + float4 weight staging):
// h0 = relu(concat(emb[z],t)@rw1+rb1)@rw2+rb2 -> g_h and g_agg.
// ---------------------------------------------------------------------------
#define INIT_SMEM_FLOATS (65 * 64 + 4096 + 64 + 64 + 64 * 68)
__global__ void __launch_bounds__(256) init_kernel(
    const int* __restrict__ z,
    const float* __restrict__ t,
    const float* __restrict__ emb,
    const float* __restrict__ W1, const float* __restrict__ b1,
    const float* __restrict__ W2, const float* __restrict__ b2,
    float* __restrict__ out1, float* __restrict__ out2)
{
    extern __shared__ float sm[];
    float* sW1 = sm;                    // 65*64 = 4160
    float* sW2 = sm + 4160;             // 64*64
    float* sb1 = sm + 8256;             // 64
    float* sb2 = sm + 8320;             // 64
    float* sIn = sm + 8384;             // [node][68] (65 used)
    __shared__ int sZ[64];

    const int tid = threadIdx.x;
    const int base = blockIdx.x * 64;

    // float4 staging: 4160 floats = 1040 float4; 4096 floats = 1024 float4
    {
        const float4* W1v = (const float4*)W1;
        const float4* W2v = (const float4*)W2;
        float4* sW1v = (float4*)sW1;
        float4* sW2v = (float4*)sW2;
#pragma unroll
        for (int i = 0; i < 4; i++) {
            sW1v[tid + 256 * i] = W1v[tid + 256 * i];
            sW2v[tid + 256 * i] = W2v[tid + 256 * i];
        }
        if (tid < 16) sW1v[tid + 1024] = W1v[tid + 1024];
    }
    if (tid < 64) {
        sb1[tid] = b1[tid]; sb2[tid] = b2[tid];
        int nd = base + tid;
        sZ[tid] = (nd < NN) ? z[nd] : 0;
        sIn[tid * 68 + 64] = (nd < NN) ? t[nd] : 0.f;
    }
    __syncthreads();

    for (int i = tid; i < 64 * 16; i += 256) {
        int nd = i >> 4, c = i & 15;
        float4 v = ((const float4*)emb)[(size_t)sZ[nd] * 16 + c];
        ((float4*)(sIn + nd * 68))[c] = v;
    }
    __syncthreads();

    const int w = tid >> 5, l = tid & 31;
    const int ln0 = w * 8;

    ull acc0[8], acc1[8];
    {
        ull bb0 = pk2(sb1[l], 0.f);
        ull bb1 = pk2(sb1[l + 32], 0.f);
#pragma unroll
        for (int j = 0; j < 8; j++) { acc0[j] = bb0; acc1[j] = bb1; }
    }

#pragma unroll 8
    for (int k = 0; k < 64; k += 2) {
        ull w0p = pk2(sW1[k * 64 + l],      sW1[(k + 1) * 64 + l]);
        ull w1p = pk2(sW1[k * 64 + l + 32], sW1[(k + 1) * 64 + l + 32]);
#pragma unroll
        for (int j = 0; j < 8; j++) {
            ull vp = *(const ull*)&sIn[(ln0 + j) * 68 + k];
            acc0[j] = ffma2(vp, w0p, acc0[j]);
            acc1[j] = ffma2(vp, w1p, acc1[j]);
        }
    }
    {   // k = 64 tail (the t column): packed (v,0)*(w,w) adds to lo only
        ull w0p = pk2(sW1[64 * 64 + l],      sW1[64 * 64 + l]);
        ull w1p = pk2(sW1[64 * 64 + l + 32], sW1[64 * 64 + l + 32]);
#pragma unroll
        for (int j = 0; j < 8; j++) {
            ull vp = pk2(sIn[(ln0 + j) * 68 + 64], 0.f);
            acc0[j] = ffma2(vp, w0p, acc0[j]);
            acc1[j] = ffma2(vp, w1p, acc1[j]);
        }
    }

    __syncwarp();
#pragma unroll
    for (int j = 0; j < 8; j++) {
        float x0, x1, y0, y1;
        upk2(acc0[j], x0, x1);
        upk2(acc1[j], y0, y1);
        sIn[(ln0 + j) * 68 + l]      = frelu(x0 + x1);
        sIn[(ln0 + j) * 68 + l + 32] = frelu(y0 + y1);
    }
    __syncwarp();

    {
        ull bb0 = pk2(sb2[l], 0.f);
        ull bb1 = pk2(sb2[l + 32], 0.f);
#pragma unroll
        for (int j = 0; j < 8; j++) { acc0[j] = bb0; acc1[j] = bb1; }
    }

#pragma unroll 8
    for (int k = 0; k < 64; k += 2) {
        ull w0p = pk2(sW2[k * 64 + l],      sW2[(k + 1) * 64 + l]);
        ull w1p = pk2(sW2[k * 64 + l + 32], sW2[(k + 1) * 64 + l + 32]);
#pragma unroll
        for (int j = 0; j < 8; j++) {
            ull vp = *(const ull*)&sIn[(ln0 + j) * 68 + k];
            acc0[j] = ffma2(vp, w0p, acc0[j]);
            acc1[j] = ffma2(vp, w1p, acc1[j]);
        }
    }

#pragma unroll
    for (int j = 0; j < 8; j++) {
        int nd = base + ln0 + j;
        if (nd < NN) {
            float x0, x1, y0, y1;
            upk2(acc0[j], x0, x1);
            upk2(acc1[j], y0, y1);
            float v0 = x0 + x1, v1 = y0 + y1;
            out1[(size_t)nd * 64 + l] = v0;
            out1[(size_t)nd * 64 + l + 32] = v1;
            out2[(size_t)nd * 64 + l] = v0;
            out2[(size_t)nd * 64 + l + 32] = v1;
        }
    }
}

// ---------------------------------------------------------------------------
// Launch
// ---------------------------------------------------------------------------
extern "C" void kernel_launch(void* const* d_in, const int* in_sizes, int n_in,
                              void* d_out, int out_size)
{
    const int*   z    = (const int*)  d_in[0];
    const int*   ei   = (const int*)  d_in[1];   // [2, E]: src = ei, dst = ei + EE
    const float* ea   = (const float*)d_in[2];
    const float* t    = (const float*)d_in[3];
    const float* emb  = (const float*)d_in[4];
    const float* rw1  = (const float*)d_in[5];
    const float* rb1  = (const float*)d_in[6];
    const float* rw2  = (const float*)d_in[7];
    const float* rb2  = (const float*)d_in[8];
    const float* cw1  = (const float*)d_in[9];
    const float* cb1  = (const float*)d_in[10];
    const float* cw2  = (const float*)d_in[11];
    const float* cb2  = (const float*)d_in[12];
    float* out = (float*)d_out;

    float* hp = nullptr;
    float* ap = nullptr;
    cudaGetSymbolAddress((void**)&hp, g_h);
    cudaGetSymbolAddress((void**)&ap, g_agg);

    const int init_smem = INIT_SMEM_FLOATS * sizeof(float);
    const int mlp_smem  = MLP_SMEM_FLOATS * sizeof(float);
    cudaFuncSetAttribute(init_kernel, cudaFuncAttributeMaxDynamicSharedMemorySize, init_smem);
    cudaFuncSetAttribute(mlp_kernel,  cudaFuncAttributeMaxDynamicSharedMemorySize, mlp_smem);

    const int nblk_node = (NN + 63) / 64;
    const int nblk_edge = (EE * 8) / 256;   // 50000 exact

    init_kernel<<<nblk_node, 256, init_smem>>>(z, t, emb, rw1, rb1, rw2, rb2, hp, ap);

    for (int li = 0; li < 3; li++) {
        edge_kernel<<<nblk_edge, 256>>>((const float4*)hp, (const float4*)ea,
                                        ei, ei + EE, (float4*)ap);
        const float* W1 = cw1 + li * 4096;
        const float* b1 = cb1 + li * 64;
        const float* W2 = cw2 + li * 4096;
        const float* b2 = cb2 + li * 64;
        if (li < 2) {
            mlp_kernel<<<nblk_node, 256, mlp_smem>>>(ap, hp, W1, b1, W2, b2, hp, ap, 1);
        } else {
            mlp_kernel<<<nblk_node, 256, mlp_smem>>>(ap, hp, W1, b1, W2, b2, out, nullptr, 0);
        }
    }
}

// round 13
// speedup vs baseline: 1.7145x; 1.0589x over previous
#include <cuda_runtime.h>
#include <cuda_bf16.h>

#define NN 100000
#define EE 1600000
#define HH 64

// Scratch (device globals; no allocation allowed)
__device__ float g_h[NN * HH];
__device__ float g_agg[NN * HH];

__device__ __forceinline__ float frelu(float x) { return x > 0.f ? x : 0.f; }

typedef unsigned long long ull;
typedef unsigned int uint;

// ---- packed f32x2 helpers (FFMA2 — only reachable via PTX) -----------------
__device__ __forceinline__ ull pk2(float lo, float hi) {
    ull r;
    asm("mov.b64 %0, {%1,%2};" : "=l"(r) : "f"(lo), "f"(hi));
    return r;
}
__device__ __forceinline__ void upk2(ull v, float& lo, float& hi) {
    asm("mov.b64 {%0,%1}, %2;" : "=f"(lo), "=f"(hi) : "l"(v));
}
__device__ __forceinline__ ull ffma2(ull a, ull b, ull c) {
    ull d;
    asm("fma.rn.f32x2 %0, %1, %2, %3;" : "=l"(d) : "l"(a), "l"(b), "l"(c));
    return d;
}

// ---- bf16 split helpers ----------------------------------------------------
__device__ __forceinline__ void split1(float a, __nv_bfloat16& h, __nv_bfloat16& l) {
    h = __float2bfloat16(a);
    l = __float2bfloat16(a - __bfloat162float(h));
}
// split two floats -> packed hi uint (lower=first elem) and packed lo uint
__device__ __forceinline__ void split2(float a, float b, uint& hi, uint& lo) {
    __nv_bfloat16 ha, la, hb, lb;
    split1(a, ha, la);
    split1(b, hb, lb);
    hi = (uint)__bfloat16_as_ushort(ha) | ((uint)__bfloat16_as_ushort(hb) << 16);
    lo = (uint)__bfloat16_as_ushort(la) | ((uint)__bfloat16_as_ushort(lb) << 16);
}

// ---- mma.sync m16n8k16 bf16 (fp32 accum) ----------------------------------
__device__ __forceinline__ void mma16816(float* c, const uint* a, uint b0, uint b1) {
    asm volatile(
        "mma.sync.aligned.m16n8k16.row.col.f32.bf16.bf16.f32 "
        "{%0,%1,%2,%3}, {%4,%5,%6,%7}, {%8,%9}, {%0,%1,%2,%3};"
        : "+f"(c[0]), "+f"(c[1]), "+f"(c[2]), "+f"(c[3])
        : "r"(a[0]), "r"(a[1]), "r"(a[2]), "r"(a[3]), "r"(b0), "r"(b1));
}

// ---------------------------------------------------------------------------
// Edge kernel (R12, measured best): msg = relu(h[src] + edge_attr);
// agg[dst] += msg. 8 threads/edge, 2 float4 chunks each, exact grid.
// ---------------------------------------------------------------------------
__global__ void __launch_bounds__(256) edge_kernel(
    const float4* __restrict__ h,
    const float4* __restrict__ ea,
    const int* __restrict__ src,
    const int* __restrict__ dst,
    float4* __restrict__ agg)
{
    int t = blockIdx.x * 256 + threadIdx.x;
    int e = t >> 3;
    int c = t & 7;

    int s = __ldg(&src[e]);
    int d = __ldg(&dst[e]);

    float4 a0 = __ldcs(&ea[(size_t)e * 16 + c]);
    float4 a1 = __ldcs(&ea[(size_t)e * 16 + c + 8]);
    float4 h0 = __ldcg(&h[(size_t)s * 16 + c]);
    float4 h1 = __ldcg(&h[(size_t)s * 16 + c + 8]);

    float4 m0, m1;
    m0.x = frelu(a0.x + h0.x); m0.y = frelu(a0.y + h0.y);
    m0.z = frelu(a0.z + h0.z); m0.w = frelu(a0.w + h0.w);
    m1.x = frelu(a1.x + h1.x); m1.y = frelu(a1.y + h1.y);
    m1.z = frelu(a1.z + h1.z); m1.w = frelu(a1.w + h1.w);

    atomicAdd(&agg[(size_t)d * 16 + c], m0);
    atomicAdd(&agg[(size_t)d * 16 + c + 8], m1);
}

// ---------------------------------------------------------------------------
// Tensor-core conv MLP kernel: out = relu_opt(relu(in@W1+b1)@W2+b2) + resid
// 256 threads = 8 warps, 128 nodes/block, warp owns a 16-node m-tile.
// bf16 split-2 ("3xBF16"): D = Xh*Wh + Xl*Wh + Xh*Wl, fp32 accumulate.
// X staged split into sXh/sXl [128][64] (uint pairs, row stride SX=35 uints);
// W staged TRANSPOSED+split into sW*h/sW*l [n][k] (stride SW=35 uints).
// Mid layer: relu + re-split in place (warp-private rows, syncwarp only).
// ---------------------------------------------------------------------------
#define SX 35
#define SW 35
#define OFF_XH  0
#define OFF_XL  (OFF_XH + 128 * SX)
#define OFF_W1H (OFF_XL + 128 * SX)
#define OFF_W1L (OFF_W1H + 64 * SW)
#define OFF_W2H (OFF_W1L + 64 * SW)
#define OFF_W2L (OFF_W2H + 64 * SW)
#define OFF_B1  (OFF_W2L + 64 * SW)
#define OFF_B2  (OFF_B1 + 64)
#define TC_SMEM_UINTS (OFF_B2 + 64)
#define TC_SMEM_BYTES (TC_SMEM_UINTS * 4)

__global__ void __launch_bounds__(256) mlp_kernel(
    const float* __restrict__ in,
    const float* __restrict__ resid,
    const float* __restrict__ W1, const float* __restrict__ b1,
    const float* __restrict__ W2, const float* __restrict__ b2,
    float* __restrict__ out1, float* __restrict__ out2,
    int relu_out)
{
    extern __shared__ uint su[];
    uint* sXh  = su + OFF_XH;
    uint* sXl  = su + OFF_XL;
    uint* sW1h = su + OFF_W1H;
    uint* sW1l = su + OFF_W1L;
    uint* sW2h = su + OFF_W2H;
    uint* sW2l = su + OFF_W2L;
    float* sb1 = (float*)(su + OFF_B1);
    float* sb2 = (float*)(su + OFF_B2);
    __nv_bfloat16* w1h_b = (__nv_bfloat16*)sW1h;  // [n][k], row stride 70 bf16
    __nv_bfloat16* w1l_b = (__nv_bfloat16*)sW1l;
    __nv_bfloat16* w2h_b = (__nv_bfloat16*)sW2h;
    __nv_bfloat16* w2l_b = (__nv_bfloat16*)sW2l;

    const int tid = threadIdx.x;
    const int base = blockIdx.x * 128;

    // ---- stage X: split into hi/lo bf16 pairs -----------------------------
    for (int i = tid; i < 128 * 16; i += 256) {
        int nd = i >> 4, c = i & 15;      // c = float4 index within row
        float4 v = make_float4(0.f, 0.f, 0.f, 0.f);
        if (base + nd < NN) v = ((const float4*)in)[(size_t)(base + nd) * 16 + c];
        uint h0, l0, h1, l1;
        split2(v.x, v.y, h0, l0);
        split2(v.z, v.w, h1, l1);
        sXh[nd * SX + 2 * c]     = h0;
        sXh[nd * SX + 2 * c + 1] = h1;
        sXl[nd * SX + 2 * c]     = l0;
        sXl[nd * SX + 2 * c + 1] = l1;
    }

    // ---- stage W1/W2: transpose [k][n]->[n][k] + split --------------------
    for (int i = tid; i < 1024; i += 256) {
        int k = i >> 4, c = i & 15;
        int n0 = 4 * c;
        float4 v1 = ((const float4*)W1)[i];
        float4 v2 = ((const float4*)W2)[i];
        __nv_bfloat16 hh, ll;
        split1(v1.x, hh, ll); w1h_b[(n0 + 0) * 70 + k] = hh; w1l_b[(n0 + 0) * 70 + k] = ll;
        split1(v1.y, hh, ll); w1h_b[(n0 + 1) * 70 + k] = hh; w1l_b[(n0 + 1) * 70 + k] = ll;
        split1(v1.z, hh, ll); w1h_b[(n0 + 2) * 70 + k] = hh; w1l_b[(n0 + 2) * 70 + k] = ll;
        split1(v1.w, hh, ll); w1h_b[(n0 + 3) * 70 + k] = hh; w1l_b[(n0 + 3) * 70 + k] = ll;
        split1(v2.x, hh, ll); w2h_b[(n0 + 0) * 70 + k] = hh; w2l_b[(n0 + 0) * 70 + k] = ll;
        split1(v2.y, hh, ll); w2h_b[(n0 + 1) * 70 + k] = hh; w2l_b[(n0 + 1) * 70 + k] = ll;
        split1(v2.z, hh, ll); w2h_b[(n0 + 2) * 70 + k] = hh; w2l_b[(n0 + 2) * 70 + k] = ll;
        split1(v2.w, hh, ll); w2h_b[(n0 + 3) * 70 + k] = hh; w2l_b[(n0 + 3) * 70 + k] = ll;
    }
    if (tid < 64) { sb1[tid] = b1[tid]; sb2[tid] = b2[tid]; }
    __syncthreads();

    const int w = tid >> 5, l = tid & 31;
    const int g = l >> 2, tig = l & 3;
    const int wn = w * 16;                // warp's 16-node tile start row

    float acc[8][4];

    // ================= GEMM 1: mid = X @ W1 + b1 =========================
#pragma unroll
    for (int nt = 0; nt < 8; nt++) {
        float bA = sb1[nt * 8 + 2 * tig];
        float bB = sb1[nt * 8 + 2 * tig + 1];
        acc[nt][0] = bA; acc[nt][1] = bB; acc[nt][2] = bA; acc[nt][3] = bB;
    }
#pragma unroll
    for (int kt = 0; kt < 4; kt++) {
        uint ah[4], al[4];
        int r0 = (wn + g) * SX + kt * 8 + tig;
        int r1 = (wn + g + 8) * SX + kt * 8 + tig;
        ah[0] = sXh[r0]; ah[1] = sXh[r1]; ah[2] = sXh[r0 + 4]; ah[3] = sXh[r1 + 4];
        al[0] = sXl[r0]; al[1] = sXl[r1]; al[2] = sXl[r0 + 4]; al[3] = sXl[r1 + 4];
#pragma unroll
        for (int nt = 0; nt < 8; nt++) {
            int bo = (nt * 8 + g) * SW + kt * 8 + tig;
            uint bh0 = sW1h[bo], bh1 = sW1h[bo + 4];
            uint bl0 = sW1l[bo], bl1 = sW1l[bo + 4];
            mma16816(acc[nt], ah, bh0, bh1);
            mma16816(acc[nt], al, bh0, bh1);
            mma16816(acc[nt], ah, bl0, bl1);
        }
    }

    // ---- mid: relu, re-split into warp-private rows of sXh/sXl -----------
    __syncwarp();
#pragma unroll
    for (int nt = 0; nt < 8; nt++) {
        float v0 = frelu(acc[nt][0]), v1 = frelu(acc[nt][1]);
        float v2 = frelu(acc[nt][2]), v3 = frelu(acc[nt][3]);
        uint h0, l0, h2, l2;
        split2(v0, v1, h0, l0);
        split2(v2, v3, h2, l2);
        sXh[(wn + g) * SX + nt * 4 + tig]     = h0;
        sXl[(wn + g) * SX + nt * 4 + tig]     = l0;
        sXh[(wn + g + 8) * SX + nt * 4 + tig] = h2;
        sXl[(wn + g + 8) * SX + nt * 4 + tig] = l2;
    }
    __syncwarp();

    // ================= GEMM 2: out = mid @ W2 + b2 =======================
#pragma unroll
    for (int nt = 0; nt < 8; nt++) {
        float bA = sb2[nt * 8 + 2 * tig];
        float bB = sb2[nt * 8 + 2 * tig + 1];
        acc[nt][0] = bA; acc[nt][1] = bB; acc[nt][2] = bA; acc[nt][3] = bB;
    }
#pragma unroll
    for (int kt = 0; kt < 4; kt++) {
        uint ah[4], al[4];
        int r0 = (wn + g) * SX + kt * 8 + tig;
        int r1 = (wn + g + 8) * SX + kt * 8 + tig;
        ah[0] = sXh[r0]; ah[1] = sXh[r1]; ah[2] = sXh[r0 + 4]; ah[3] = sXh[r1 + 4];
        al[0] = sXl[r0]; al[1] = sXl[r1]; al[2] = sXl[r0 + 4]; al[3] = sXl[r1 + 4];
#pragma unroll
        for (int nt = 0; nt < 8; nt++) {
            int bo = (nt * 8 + g) * SW + kt * 8 + tig;
            uint bh0 = sW2h[bo], bh1 = sW2h[bo + 4];
            uint bl0 = sW2l[bo], bl1 = sW2l[bo + 4];
            mma16816(acc[nt], ah, bh0, bh1);
            mma16816(acc[nt], al, bh0, bh1);
            mma16816(acc[nt], ah, bl0, bl1);
        }
    }

    // ---- epilogue: optional relu, + resid, store --------------------------
    const int n0 = base + wn + g;
    const int n1 = n0 + 8;
#pragma unroll
    for (int nt = 0; nt < 8; nt++) {
        int col = nt * 8 + 2 * tig;
        if (n0 < NN) {
            float v0 = acc[nt][0], v1 = acc[nt][1];
            if (relu_out) { v0 = frelu(v0); v1 = frelu(v1); }
            float2 r = *(const float2*)&resid[(size_t)n0 * 64 + col];
            float2 o = make_float2(v0 + r.x, v1 + r.y);
            *(float2*)&out1[(size_t)n0 * 64 + col] = o;
            if (out2) *(float2*)&out2[(size_t)n0 * 64 + col] = o;
        }
        if (n1 < NN) {
            float v2 = acc[nt][2], v3 = acc[nt][3];
            if (relu_out) { v2 = frelu(v2); v3 = frelu(v3); }
            float2 r = *(const float2*)&resid[(size_t)n1 * 64 + col];
            float2 o = make_float2(v2 + r.x, v3 + r.y);
            *(float2*)&out1[(size_t)n1 * 64 + col] = o;
            if (out2) *(float2*)&out2[(size_t)n1 * 64 + col] = o;
        }
    }
}

// ---------------------------------------------------------------------------
// Init kernel (R12, FFMA2): h0 = relu(concat(emb[z],t)@rw1+rb1)@rw2+rb2
// -> g_h and g_agg.
// ---------------------------------------------------------------------------
#define INIT_SMEM_FLOATS (65 * 64 + 4096 + 64 + 64 + 64 * 68)
__global__ void __launch_bounds__(256) init_kernel(
    const int* __restrict__ z,
    const float* __restrict__ t,
    const float* __restrict__ emb,
    const float* __restrict__ W1, const float* __restrict__ b1,
    const float* __restrict__ W2, const float* __restrict__ b2,
    float* __restrict__ out1, float* __restrict__ out2)
{
    extern __shared__ float sm[];
    float* sW1 = sm;                    // 65*64 = 4160
    float* sW2 = sm + 4160;             // 64*64
    float* sb1 = sm + 8256;             // 64
    float* sb2 = sm + 8320;             // 64
    float* sIn = sm + 8384;             // [node][68] (65 used)
    __shared__ int sZ[64];

    const int tid = threadIdx.x;
    const int base = blockIdx.x * 64;

    {
        const float4* W1v = (const float4*)W1;
        const float4* W2v = (const float4*)W2;
        float4* sW1v = (float4*)sW1;
        float4* sW2v = (float4*)sW2;
#pragma unroll
        for (int i = 0; i < 4; i++) {
            sW1v[tid + 256 * i] = W1v[tid + 256 * i];
            sW2v[tid + 256 * i] = W2v[tid + 256 * i];
        }
        if (tid < 16) sW1v[tid + 1024] = W1v[tid + 1024];
    }
    if (tid < 64) {
        sb1[tid] = b1[tid]; sb2[tid] = b2[tid];
        int nd = base + tid;
        sZ[tid] = (nd < NN) ? z[nd] : 0;
        sIn[tid * 68 + 64] = (nd < NN) ? t[nd] : 0.f;
    }
    __syncthreads();

    for (int i = tid; i < 64 * 16; i += 256) {
        int nd = i >> 4, c = i & 15;
        float4 v = ((const float4*)emb)[(size_t)sZ[nd] * 16 + c];
        ((float4*)(sIn + nd * 68))[c] = v;
    }
    __syncthreads();

    const int w = tid >> 5, l = tid & 31;
    const int ln0 = w * 8;

    ull acc0[8], acc1[8];
    {
        ull bb0 = pk2(sb1[l], 0.f);
        ull bb1 = pk2(sb1[l + 32], 0.f);
#pragma unroll
        for (int j = 0; j < 8; j++) { acc0[j] = bb0; acc1[j] = bb1; }
    }

#pragma unroll 8
    for (int k = 0; k < 64; k += 2) {
        ull w0p = pk2(sW1[k * 64 + l],      sW1[(k + 1) * 64 + l]);
        ull w1p = pk2(sW1[k * 64 + l + 32], sW1[(k + 1) * 64 + l + 32]);
#pragma unroll
        for (int j = 0; j < 8; j++) {
            ull vp = *(const ull*)&sIn[(ln0 + j) * 68 + k];
            acc0[j] = ffma2(vp, w0p, acc0[j]);
            acc1[j] = ffma2(vp, w1p, acc1[j]);
        }
    }
    {   // k = 64 tail (the t column): packed (v,0)*(w,w) adds to lo only
        ull w0p = pk2(sW1[64 * 64 + l],      sW1[64 * 64 + l]);
        ull w1p = pk2(sW1[64 * 64 + l + 32], sW1[64 * 64 + l + 32]);
#pragma unroll
        for (int j = 0; j < 8; j++) {
            ull vp = pk2(sIn[(ln0 + j) * 68 + 64], 0.f);
            acc0[j] = ffma2(vp, w0p, acc0[j]);
            acc1[j] = ffma2(vp, w1p, acc1[j]);
        }
    }

    __syncwarp();
#pragma unroll
    for (int j = 0; j < 8; j++) {
        float x0, x1, y0, y1;
        upk2(acc0[j], x0, x1);
        upk2(acc1[j], y0, y1);
        sIn[(ln0 + j) * 68 + l]      = frelu(x0 + x1);
        sIn[(ln0 + j) * 68 + l + 32] = frelu(y0 + y1);
    }
    __syncwarp();

    {
        ull bb0 = pk2(sb2[l], 0.f);
        ull bb1 = pk2(sb2[l + 32], 0.f);
#pragma unroll
        for (int j = 0; j < 8; j++) { acc0[j] = bb0; acc1[j] = bb1; }
    }

#pragma unroll 8
    for (int k = 0; k < 64; k += 2) {
        ull w0p = pk2(sW2[k * 64 + l],      sW2[(k + 1) * 64 + l]);
        ull w1p = pk2(sW2[k * 64 + l + 32], sW2[(k + 1) * 64 + l + 32]);
#pragma unroll
        for (int j = 0; j < 8; j++) {
            ull vp = *(const ull*)&sIn[(ln0 + j) * 68 + k];
            acc0[j] = ffma2(vp, w0p, acc0[j]);
            acc1[j] = ffma2(vp, w1p, acc1[j]);
        }
    }

#pragma unroll
    for (int j = 0; j < 8; j++) {
        int nd = base + ln0 + j;
        if (nd < NN) {
            float x0, x1, y0, y1;
            upk2(acc0[j], x0, x1);
            upk2(acc1[j], y0, y1);
            float v0 = x0 + x1, v1 = y0 + y1;
            out1[(size_t)nd * 64 + l] = v0;
            out1[(size_t)nd * 64 + l + 32] = v1;
            out2[(size_t)nd * 64 + l] = v0;
            out2[(size_t)nd * 64 + l + 32] = v1;
        }
    }
}

// ---------------------------------------------------------------------------
// Launch
// ---------------------------------------------------------------------------
extern "C" void kernel_launch(void* const* d_in, const int* in_sizes, int n_in,
                              void* d_out, int out_size)
{
    const int*   z    = (const int*)  d_in[0];
    const int*   ei   = (const int*)  d_in[1];   // [2, E]: src = ei, dst = ei + EE
    const float* ea   = (const float*)d_in[2];
    const float* t    = (const float*)d_in[3];
    const float* emb  = (const float*)d_in[4];
    const float* rw1  = (const float*)d_in[5];
    const float* rb1  = (const float*)d_in[6];
    const float* rw2  = (const float*)d_in[7];
    const float* rb2  = (const float*)d_in[8];
    const float* cw1  = (const float*)d_in[9];
    const float* cb1  = (const float*)d_in[10];
    const float* cw2  = (const float*)d_in[11];
    const float* cb2  = (const float*)d_in[12];
    float* out = (float*)d_out;

    float* hp = nullptr;
    float* ap = nullptr;
    cudaGetSymbolAddress((void**)&hp, g_h);
    cudaGetSymbolAddress((void**)&ap, g_agg);

    const int init_smem = INIT_SMEM_FLOATS * sizeof(float);
    cudaFuncSetAttribute(init_kernel, cudaFuncAttributeMaxDynamicSharedMemorySize, init_smem);
    cudaFuncSetAttribute(mlp_kernel,  cudaFuncAttributeMaxDynamicSharedMemorySize, TC_SMEM_BYTES);

    const int nblk_init = (NN + 63) / 64;
    const int nblk_mlp  = (NN + 127) / 128;
    const int nblk_edge = (EE * 8) / 256;   // 50000 exact

    init_kernel<<<nblk_init, 256, init_smem>>>(z, t, emb, rw1, rb1, rw2, rb2, hp, ap);

    for (int li = 0; li < 3; li++) {
        edge_kernel<<<nblk_edge, 256>>>((const float4*)hp, (const float4*)ea,
                                        ei, ei + EE, (float4*)ap);
        const float* W1 = cw1 + li * 4096;
        const float* b1 = cb1 + li * 64;
        const float* W2 = cw2 + li * 4096;
        const float* b2 = cb2 + li * 64;
        if (li < 2) {
            mlp_kernel<<<nblk_mlp, 256, TC_SMEM_BYTES>>>(ap, hp, W1, b1, W2, b2, hp, ap, 1);
        } else {
            mlp_kernel<<<nblk_mlp, 256, TC_SMEM_BYTES>>>(ap, hp, W1, b1, W2, b2, out, nullptr, 0);
        }
    }
}

// round 14
// speedup vs baseline: 1.7387x; 1.0141x over previous
#include <cuda_runtime.h>
#include <cuda_bf16.h>

#define NN 100000
#define EE 1600000
#define HH 64

typedef unsigned long long ull;
typedef unsigned int uint;

// Scratch (device globals; no allocation allowed)
__device__ float g_h[NN * HH];
__device__ float g_agg[NN * HH];
__device__ uint  g_wsplit[4 * 8960];   // per "layer": W1h,W1l,W2h,W2l planes, 2240 uints each

__device__ __forceinline__ float frelu(float x) { return x > 0.f ? x : 0.f; }

// ---- bf16 split helpers ----------------------------------------------------
__device__ __forceinline__ void split1(float a, __nv_bfloat16& h, __nv_bfloat16& l) {
    h = __float2bfloat16(a);
    l = __float2bfloat16(a - __bfloat162float(h));
}
__device__ __forceinline__ void split2(float a, float b, uint& hi, uint& lo) {
    __nv_bfloat16 ha, la, hb, lb;
    split1(a, ha, la);
    split1(b, hb, lb);
    hi = (uint)__bfloat16_as_ushort(ha) | ((uint)__bfloat16_as_ushort(hb) << 16);
    lo = (uint)__bfloat16_as_ushort(la) | ((uint)__bfloat16_as_ushort(lb) << 16);
}

// ---- mma.sync m16n8k16 bf16 (fp32 accum) ----------------------------------
__device__ __forceinline__ void mma16816(float* c, const uint* a, uint b0, uint b1) {
    asm volatile(
        "mma.sync.aligned.m16n8k16.row.col.f32.bf16.bf16.f32 "
        "{%0,%1,%2,%3}, {%4,%5,%6,%7}, {%8,%9}, {%0,%1,%2,%3};"
        : "+f"(c[0]), "+f"(c[1]), "+f"(c[2]), "+f"(c[3])
        : "r"(a[0]), "r"(a[1]), "r"(a[2]), "r"(a[3]), "r"(b0), "r"(b1));
}

// ---------------------------------------------------------------------------
// prep_weights: split-2 + transpose all 4 MLPs' weights into global planes
// laid out exactly as the TC kernel's smem region expects.
// layer 0..2 = conv layers; layer 3 = init (rw1 rows 0..63, rw2).
// dest uint [layer*8960 + mat01*4480 + plane*2240 + n*35 + j] holds bf16 pair
// (W[2j][n], W[2j+1][n]) of the hi (plane 0) or lo (plane 1) split.
// ---------------------------------------------------------------------------
__global__ void __launch_bounds__(256) prep_weights(
    const float* __restrict__ cw1, const float* __restrict__ cw2,
    const float* __restrict__ rw1, const float* __restrict__ rw2,
    uint* __restrict__ gw)
{
    int idx = blockIdx.x * 256 + threadIdx.x;
    if (idx >= 4 * 2 * 64 * 32) return;
    int layer = idx >> 12;
    int mat01 = (idx >> 11) & 1;
    int n     = (idx >> 5) & 63;
    int j     = idx & 31;

    const float* W;
    if (layer < 3) W = mat01 ? (cw2 + layer * 4096) : (cw1 + layer * 4096);
    else           W = mat01 ? rw2 : rw1;

    float a = W[(2 * j) * 64 + n];
    float b = W[(2 * j + 1) * 64 + n];
    uint hu, lu;
    split2(a, b, hu, lu);
    int base = layer * 8960 + mat01 * 4480;
    gw[base + n * 35 + j]        = hu;
    gw[base + 2240 + n * 35 + j] = lu;
}

// ---------------------------------------------------------------------------
// Edge kernel (R12, measured best): msg = relu(h[src] + edge_attr);
// agg[dst] += msg. 8 threads/edge, 2 float4 chunks each, exact grid.
// ---------------------------------------------------------------------------
__global__ void __launch_bounds__(256) edge_kernel(
    const float4* __restrict__ h,
    const float4* __restrict__ ea,
    const int* __restrict__ src,
    const int* __restrict__ dst,
    float4* __restrict__ agg)
{
    int t = blockIdx.x * 256 + threadIdx.x;
    int e = t >> 3;
    int c = t & 7;

    int s = __ldg(&src[e]);
    int d = __ldg(&dst[e]);

    float4 a0 = __ldcs(&ea[(size_t)e * 16 + c]);
    float4 a1 = __ldcs(&ea[(size_t)e * 16 + c + 8]);
    float4 h0 = __ldcg(&h[(size_t)s * 16 + c]);
    float4 h1 = __ldcg(&h[(size_t)s * 16 + c + 8]);

    float4 m0, m1;
    m0.x = frelu(a0.x + h0.x); m0.y = frelu(a0.y + h0.y);
    m0.z = frelu(a0.z + h0.z); m0.w = frelu(a0.w + h0.w);
    m1.x = frelu(a1.x + h1.x); m1.y = frelu(a1.y + h1.y);
    m1.z = frelu(a1.z + h1.z); m1.w = frelu(a1.w + h1.w);

    atomicAdd(&agg[(size_t)d * 16 + c], m0);
    atomicAdd(&agg[(size_t)d * 16 + c + 8], m1);
}

// ---------------------------------------------------------------------------
// Tensor-core MLP kernel (conv layers AND init):
//   out = relu_opt(relu(X@W1 + b1 [+ t*rw1_row64])@W2 + b2) [+ resid]
// X source: zidx ? emb[zidx[node]] (init) : in[node] (conv).
// 256 threads = 8 warps, 128 nodes/block, warp owns a 16-node m-tile.
// bf16 split-2: D = Xh*Wh + Xl*Wh + Xh*Wl, fp32 accumulate.
// Weights pre-split/transposed by prep_weights -> flat float4 smem copy.
// ---------------------------------------------------------------------------
#define SX 35
#define SW 35
#define OFF_XH  0
#define OFF_XL  (OFF_XH + 128 * SX)       // 4480
#define OFF_W   (OFF_XL + 128 * SX)       // 8960: W1h,W1l,W2h,W2l contiguous
#define OFF_B1  (OFF_W + 4 * 2240)        // 17920
#define OFF_B2  (OFF_B1 + 64)
#define OFF_T   (OFF_B2 + 64)             // 128 floats
#define OFF_W64 (OFF_T + 128)             // 64 floats
#define TC_SMEM_UINTS (OFF_W64 + 64)
#define TC_SMEM_BYTES (TC_SMEM_UINTS * 4)

__global__ void __launch_bounds__(256) mlp_kernel(
    const float* __restrict__ in,
    const int* __restrict__ zidx,
    const float* __restrict__ emb,
    const float* __restrict__ tvec,
    const float* __restrict__ w64,
    const uint* __restrict__ wsp,       // this layer's 8960-uint split-weight block
    const float* __restrict__ b1, const float* __restrict__ b2,
    const float* __restrict__ resid,
    float* __restrict__ out1, float* __restrict__ out2,
    int relu_out)
{
    extern __shared__ uint su[];
    uint* sXh  = su + OFF_XH;
    uint* sXl  = su + OFF_XL;
    uint* sW1h = su + OFF_W;
    uint* sW1l = su + OFF_W + 2240;
    uint* sW2h = su + OFF_W + 4480;
    uint* sW2l = su + OFF_W + 6720;
    float* sb1 = (float*)(su + OFF_B1);
    float* sb2 = (float*)(su + OFF_B2);
    float* sT  = (float*)(su + OFF_T);
    float* sw64 = (float*)(su + OFF_W64);
    __shared__ int sZ[128];

    const int tid = threadIdx.x;
    const int base = blockIdx.x * 128;

    // ---- stage weights: flat float4 copy of the pre-split block -----------
    {
        const float4* src4 = (const float4*)wsp;
        float4* dst4 = (float4*)(su + OFF_W);
        for (int i = tid; i < 2240; i += 256) dst4[i] = src4[i];
    }
    if (tid < 64) { sb1[tid] = b1[tid]; sb2[tid] = b2[tid]; }
    if (zidx) {
        if (tid < 128) {
            int nd = base + tid;
            sZ[tid] = (nd < NN) ? zidx[nd] : 0;
            sT[tid] = (nd < NN) ? tvec[nd] : 0.f;
        }
        if (tid >= 128 && tid < 192) sw64[tid - 128] = w64[tid - 128];
        __syncthreads();   // sZ ready before emb gather below
    }

    // ---- stage X: split into hi/lo bf16 pairs -----------------------------
    for (int i = tid; i < 128 * 16; i += 256) {
        int nd = i >> 4, c = i & 15;
        float4 v = make_float4(0.f, 0.f, 0.f, 0.f);
        if (base + nd < NN) {
            if (zidx) v = ((const float4*)emb)[(size_t)sZ[nd] * 16 + c];
            else      v = ((const float4*)in)[(size_t)(base + nd) * 16 + c];
        }
        uint h0, l0, h1, l1;
        split2(v.x, v.y, h0, l0);
        split2(v.z, v.w, h1, l1);
        sXh[nd * SX + 2 * c]     = h0;
        sXh[nd * SX + 2 * c + 1] = h1;
        sXl[nd * SX + 2 * c]     = l0;
        sXl[nd * SX + 2 * c + 1] = l1;
    }
    __syncthreads();

    const int w = tid >> 5, l = tid & 31;
    const int g = l >> 2, tig = l & 3;
    const int wn = w * 16;

    float acc[8][4];

    // ================= GEMM 1: mid = X @ W1 + b1 (+ t-term) ===============
    if (zidx) {
        float t0 = sT[wn + g], t8 = sT[wn + g + 8];
#pragma unroll
        for (int nt = 0; nt < 8; nt++) {
            int c0 = nt * 8 + 2 * tig, c1 = c0 + 1;
            acc[nt][0] = fmaf(t0, sw64[c0], sb1[c0]);
            acc[nt][1] = fmaf(t0, sw64[c1], sb1[c1]);
            acc[nt][2] = fmaf(t8, sw64[c0], sb1[c0]);
            acc[nt][3] = fmaf(t8, sw64[c1], sb1[c1]);
        }
    } else {
#pragma unroll
        for (int nt = 0; nt < 8; nt++) {
            float bA = sb1[nt * 8 + 2 * tig];
            float bB = sb1[nt * 8 + 2 * tig + 1];
            acc[nt][0] = bA; acc[nt][1] = bB; acc[nt][2] = bA; acc[nt][3] = bB;
        }
    }
#pragma unroll
    for (int kt = 0; kt < 4; kt++) {
        uint ah[4], al[4];
        int r0 = (wn + g) * SX + kt * 8 + tig;
        int r1 = (wn + g + 8) * SX + kt * 8 + tig;
        ah[0] = sXh[r0]; ah[1] = sXh[r1]; ah[2] = sXh[r0 + 4]; ah[3] = sXh[r1 + 4];
        al[0] = sXl[r0]; al[1] = sXl[r1]; al[2] = sXl[r0 + 4]; al[3] = sXl[r1 + 4];
#pragma unroll
        for (int nt = 0; nt < 8; nt++) {
            int bo = (nt * 8 + g) * SW + kt * 8 + tig;
            uint bh0 = sW1h[bo], bh1 = sW1h[bo + 4];
            uint bl0 = sW1l[bo], bl1 = sW1l[bo + 4];
            mma16816(acc[nt], ah, bh0, bh1);
            mma16816(acc[nt], al, bh0, bh1);
            mma16816(acc[nt], ah, bl0, bl1);
        }
    }

    // ---- mid: relu, re-split into warp-private rows -----------------------
    __syncwarp();
#pragma unroll
    for (int nt = 0; nt < 8; nt++) {
        float v0 = frelu(acc[nt][0]), v1 = frelu(acc[nt][1]);
        float v2 = frelu(acc[nt][2]), v3 = frelu(acc[nt][3]);
        uint h0, l0, h2, l2;
        split2(v0, v1, h0, l0);
        split2(v2, v3, h2, l2);
        sXh[(wn + g) * SX + nt * 4 + tig]     = h0;
        sXl[(wn + g) * SX + nt * 4 + tig]     = l0;
        sXh[(wn + g + 8) * SX + nt * 4 + tig] = h2;
        sXl[(wn + g + 8) * SX + nt * 4 + tig] = l2;
    }
    __syncwarp();

    // ================= GEMM 2: out = mid @ W2 + b2 =======================
#pragma unroll
    for (int nt = 0; nt < 8; nt++) {
        float bA = sb2[nt * 8 + 2 * tig];
        float bB = sb2[nt * 8 + 2 * tig + 1];
        acc[nt][0] = bA; acc[nt][1] = bB; acc[nt][2] = bA; acc[nt][3] = bB;
    }
#pragma unroll
    for (int kt = 0; kt < 4; kt++) {
        uint ah[4], al[4];
        int r0 = (wn + g) * SX + kt * 8 + tig;
        int r1 = (wn + g + 8) * SX + kt * 8 + tig;
        ah[0] = sXh[r0]; ah[1] = sXh[r1]; ah[2] = sXh[r0 + 4]; ah[3] = sXh[r1 + 4];
        al[0] = sXl[r0]; al[1] = sXl[r1]; al[2] = sXl[r0 + 4]; al[3] = sXl[r1 + 4];
#pragma unroll
        for (int nt = 0; nt < 8; nt++) {
            int bo = (nt * 8 + g) * SW + kt * 8 + tig;
            uint bh0 = sW2h[bo], bh1 = sW2h[bo + 4];
            uint bl0 = sW2l[bo], bl1 = sW2l[bo + 4];
            mma16816(acc[nt], ah, bh0, bh1);
            mma16816(acc[nt], al, bh0, bh1);
            mma16816(acc[nt], ah, bl0, bl1);
        }
    }

    // ---- epilogue: optional relu, optional resid, store -------------------
    const int n0 = base + wn + g;
    const int n1 = n0 + 8;
#pragma unroll
    for (int nt = 0; nt < 8; nt++) {
        int col = nt * 8 + 2 * tig;
        if (n0 < NN) {
            float v0 = acc[nt][0], v1 = acc[nt][1];
            if (relu_out) { v0 = frelu(v0); v1 = frelu(v1); }
            if (resid) {
                float2 r = *(const float2*)&resid[(size_t)n0 * 64 + col];
                v0 += r.x; v1 += r.y;
            }
            float2 o = make_float2(v0, v1);
            *(float2*)&out1[(size_t)n0 * 64 + col] = o;
            if (out2) *(float2*)&out2[(size_t)n0 * 64 + col] = o;
        }
        if (n1 < NN) {
            float v2 = acc[nt][2], v3 = acc[nt][3];
            if (relu_out) { v2 = frelu(v2); v3 = frelu(v3); }
            if (resid) {
                float2 r = *(const float2*)&resid[(size_t)n1 * 64 + col];
                v2 += r.x; v3 += r.y;
            }
            float2 o = make_float2(v2, v3);
            *(float2*)&out1[(size_t)n1 * 64 + col] = o;
            if (out2) *(float2*)&out2[(size_t)n1 * 64 + col] = o;
        }
    }
}

// ---------------------------------------------------------------------------
// Launch
// ---------------------------------------------------------------------------
extern "C" void kernel_launch(void* const* d_in, const int* in_sizes, int n_in,
                              void* d_out, int out_size)
{
    const int*   z    = (const int*)  d_in[0];
    const int*   ei   = (const int*)  d_in[1];   // [2, E]: src = ei, dst = ei + EE
    const float* ea   = (const float*)d_in[2];
    const float* t    = (const float*)d_in[3];
    const float* emb  = (const float*)d_in[4];
    const float* rw1  = (const float*)d_in[5];
    const float* rb1  = (const float*)d_in[6];
    const float* rw2  = (const float*)d_in[7];
    const float* rb2  = (const float*)d_in[8];
    const float* cw1  = (const float*)d_in[9];
    const float* cb1  = (const float*)d_in[10];
    const float* cw2  = (const float*)d_in[11];
    const float* cb2  = (const float*)d_in[12];
    float* out = (float*)d_out;

    float* hp = nullptr;
    float* ap = nullptr;
    uint*  gw = nullptr;
    cudaGetSymbolAddress((void**)&hp, g_h);
    cudaGetSymbolAddress((void**)&ap, g_agg);
    cudaGetSymbolAddress((void**)&gw, g_wsplit);

    cudaFuncSetAttribute(mlp_kernel, cudaFuncAttributeMaxDynamicSharedMemorySize, TC_SMEM_BYTES);

    const int nblk_mlp  = (NN + 127) / 128;
    const int nblk_edge = (EE * 8) / 256;   // 50000 exact

    // one-time per launch: split/transpose all weights
    prep_weights<<<64, 256>>>(cw1, cw2, rw1, rw2, gw);

    // init: TC path, X = emb[z], + t-term; writes g_h and g_agg
    mlp_kernel<<<nblk_mlp, 256, TC_SMEM_BYTES>>>(
        nullptr, z, emb, t, rw1 + 64 * 64, gw + 3 * 8960,
        rb1, rb2, nullptr, hp, ap, 0);

    for (int li = 0; li < 3; li++) {
        edge_kernel<<<nblk_edge, 256>>>((const float4*)hp, (const float4*)ea,
                                        ei, ei + EE, (float4*)ap);
        const float* b1 = cb1 + li * 64;
        const float* b2 = cb2 + li * 64;
        const uint*  wl = gw + li * 8960;
        if (li < 2) {
            mlp_kernel<<<nblk_mlp, 256, TC_SMEM_BYTES>>>(
                ap, nullptr, nullptr, nullptr, nullptr, wl, b1, b2, hp, hp, ap, 1);
        } else {
            mlp_kernel<<<nblk_mlp, 256, TC_SMEM_BYTES>>>(
                ap, nullptr, nullptr, nullptr, nullptr, wl, b1, b2, hp, out, nullptr, 0);
        }
    }
}